// round 2
// baseline (speedup 1.0000x reference)
#include <cuda_runtime.h>

#define C    128
#define HID  512
#define TT   64      // tokens per CTA
#define NTH  256
#define TPT  8       // tokens per thread
#define OPT  4       // outputs per thread
#define HW   16384   // h*w per image

struct Smem {
    float X[C][TT];     // residual t, feature-major
    float U[C][TT];     // scratch: u / y2 / k_chunk
    float Wht[C][TT];   // whitened activations
    float red1[4][TT];
    float red2[4][TT];
    float mu[TT];
    float rstd[TT];
};

// LayerNorm over the channel dim for all TT tokens; optional fused sigmoid(v)*v.
__device__ __forceinline__ void layer_norm(Smem& sm, const float (*src)[TT],
                                           float (*dst)[TT],
                                           const float* __restrict__ g,
                                           const float* __restrict__ bta,
                                           bool sigmul)
{
    const int tid  = threadIdx.x;
    const int tok  = tid & (TT - 1);
    const int part = tid >> 6;            // 0..3, each covers 32 channels
    float s1 = 0.f, s2 = 0.f;
    #pragma unroll
    for (int k = 0; k < C / 4; k++) {
        float v = src[part * (C / 4) + k][tok];
        s1 += v; s2 += v * v;
    }
    sm.red1[part][tok] = s1;
    sm.red2[part][tok] = s2;
    __syncthreads();
    if (tid < TT) {
        float a = 0.f, q = 0.f;
        #pragma unroll
        for (int p = 0; p < 4; p++) { a += sm.red1[p][tid]; q += sm.red2[p][tid]; }
        float mu  = a * (1.0f / C);
        float var = q * (1.0f / C) - mu * mu;
        sm.mu[tid]   = mu;
        sm.rstd[tid] = rsqrtf(var + 1e-5f);
    }
    __syncthreads();
    #pragma unroll
    for (int k = 0; k < (C * TT) / NTH; k++) {
        int idx = tid + k * NTH;
        int c = idx >> 6, t = idx & (TT - 1);
        float v = (src[c][t] - sm.mu[t]) * sm.rstd[t] * __ldg(g + c) + __ldg(bta + c);
        if (sigmul) {
            float s = 1.0f / (1.0f + expf(-v));
            v = s * v;
        }
        dst[c][t] = v;
    }
}

// acc[TPT][OPT] += W[rowBase + o][colOff + c] * src[c][tok]
// thread: tg = tid&7 -> tokens (tg + 8*i), og = tid>>3 -> outputs (og*4 + j)
template<int LD>
__device__ __forceinline__ void gemm_acc(float acc[TPT][OPT],
                                         const float (*src)[TT],
                                         const float* __restrict__ W,
                                         int rowBase, int colOff)
{
    const int tid = threadIdx.x;
    const int tg  = tid & 7;
    const int og  = tid >> 3;
    const float* w0 = W + (size_t)(rowBase + og * OPT) * LD + colOff;
    #pragma unroll 2
    for (int c = 0; c < C; c += 4) {
        float4 wq[OPT];
        #pragma unroll
        for (int j = 0; j < OPT; j++)
            wq[j] = __ldg(reinterpret_cast<const float4*>(w0 + j * LD + c));
        #pragma unroll
        for (int cc = 0; cc < 4; cc++) {
            float wv[OPT];
            #pragma unroll
            for (int j = 0; j < OPT; j++)
                wv[j] = reinterpret_cast<const float*>(&wq[j])[cc];
            #pragma unroll
            for (int i = 0; i < TPT; i++) {
                float xv = src[c + cc][tg + 8 * i];
                #pragma unroll
                for (int j = 0; j < OPT; j++)
                    acc[i][j] = fmaf(xv, wv[j], acc[i][j]);
            }
        }
    }
}

__device__ __forceinline__ void zero_acc(float acc[TPT][OPT]) {
    #pragma unroll
    for (int i = 0; i < TPT; i++)
        #pragma unroll
        for (int j = 0; j < OPT; j++)
            acc[i][j] = 0.f;
}

__global__ void __launch_bounds__(NTH) rwkv_kernel(
    const float* __restrict__ x,
    const float* __restrict__ ln0_g, const float* __restrict__ ln0_b,
    const float* __restrict__ ln1_g, const float* __restrict__ ln1_b,
    const float* __restrict__ ln2_g, const float* __restrict__ ln2_b,
    const float* __restrict__ Wout,  const float* __restrict__ Wwhiten,
    const float* __restrict__ Wkey,  const float* __restrict__ Wrecep,
    const float* __restrict__ Wvalue,
    float* __restrict__ out)
{
    extern __shared__ char smraw[];
    Smem& sm = *reinterpret_cast<Smem*>(smraw);
    const int tid = threadIdx.x;
    const int tg  = tid & 7;
    const int og  = tid >> 3;
    const int tile = blockIdx.x;          // 0..1023
    const int b    = tile >> 8;           // 256 tiles per image
    const int hw0  = (tile & 255) * TT;
    const float* xb = x   + (size_t)b * C * HW + hw0;
    float*       ob = out + (size_t)b * C * HW + hw0;

    // Load tile: X[c][tok] = x[b, c, hw0+tok]   (coalesced over tok)
    #pragma unroll
    for (int k = 0; k < (C * TT) / NTH; k++) {
        int idx = tid + k * NTH;
        int c = idx >> 6, t = idx & (TT - 1);
        sm.X[c][t] = xb[c * HW + t];
    }
    __syncthreads();

    // t = ln0(x)   (in place)
    layer_norm(sm, sm.X, sm.X, ln0_g, ln0_b, false);
    __syncthreads();

    // --- SpatialMix (token-wise): att = W_out @ (sigmoid(y1)*y1), y1 = ln1(t)
    layer_norm(sm, sm.X, sm.U, ln1_g, ln1_b, true);
    __syncthreads();
    float acc[TPT][OPT];
    zero_acc(acc);
    gemm_acc<C>(acc, sm.U, Wout, 0, 0);
    #pragma unroll
    for (int i = 0; i < TPT; i++)
        #pragma unroll
        for (int j = 0; j < OPT; j++)
            sm.X[og * OPT + j][tg + 8 * i] += acc[i][j];
    __syncthreads();

    // --- ChannelMix: y2 = ln2(t); wht = W_whiten @ y2
    layer_norm(sm, sm.X, sm.U, ln2_g, ln2_b, false);
    __syncthreads();
    zero_acc(acc);
    gemm_acc<C>(acc, sm.U, Wwhiten, 0, 0);
    __syncthreads();   // whiten's U reads done before U is reused for k chunks
    #pragma unroll
    for (int i = 0; i < TPT; i++)
        #pragma unroll
        for (int j = 0; j < OPT; j++)
            sm.Wht[og * OPT + j][tg + 8 * i] = acc[i][j];
    __syncthreads();

    // k = relu(W_key @ wht)^2 in 4 chunks of 128; kv += W_value[:,chunk] @ k_chunk
    float accKV[TPT][OPT];
    zero_acc(accKV);
    for (int ch = 0; ch < 4; ch++) {
        float accK[TPT][OPT];
        zero_acc(accK);
        gemm_acc<C>(accK, sm.Wht, Wkey, ch * C, 0);
        __syncthreads();                 // previous chunk's U reads done
        #pragma unroll
        for (int i = 0; i < TPT; i++)
            #pragma unroll
            for (int j = 0; j < OPT; j++) {
                float v = accK[i][j];
                v = (v > 0.f) ? v * v : 0.f;
                sm.U[og * OPT + j][tg + 8 * i] = v;
            }
        __syncthreads();
        gemm_acc<HID>(accKV, sm.U, Wvalue, 0, ch * C);
    }

    // r = sigmoid(W_recep @ wht);  out = 2 * (t + r*kv)
    float accR[TPT][OPT];
    zero_acc(accR);
    gemm_acc<C>(accR, sm.Wht, Wrecep, 0, 0);
    #pragma unroll
    for (int i = 0; i < TPT; i++)
        #pragma unroll
        for (int j = 0; j < OPT; j++) {
            float r = 1.0f / (1.0f + expf(-accR[i][j]));
            float t = sm.X[og * OPT + j][tg + 8 * i] + r * accKV[i][j];
            ob[(og * OPT + j) * HW + tg + 8 * i] = 2.0f * t;
        }
}

extern "C" void kernel_launch(void* const* d_in, const int* in_sizes, int n_in,
                              void* d_out, int out_size)
{
    const float* x       = (const float*)d_in[0];
    const float* ln0_g   = (const float*)d_in[1];
    const float* ln0_b   = (const float*)d_in[2];
    const float* ln1_g   = (const float*)d_in[3];
    const float* ln1_b   = (const float*)d_in[4];
    const float* ln2_g   = (const float*)d_in[5];
    const float* ln2_b   = (const float*)d_in[6];
    const float* Wout    = (const float*)d_in[7];
    const float* Wwhiten = (const float*)d_in[8];
    const float* Wkey    = (const float*)d_in[9];
    const float* Wrecep  = (const float*)d_in[10];
    const float* Wvalue  = (const float*)d_in[11];
    float* out = (float*)d_out;

    cudaFuncSetAttribute(rwkv_kernel,
                         cudaFuncAttributeMaxDynamicSharedMemorySize,
                         (int)sizeof(Smem));
    rwkv_kernel<<<1024, NTH, sizeof(Smem)>>>(
        x, ln0_g, ln0_b, ln1_g, ln1_b, ln2_g, ln2_b,
        Wout, Wwhiten, Wkey, Wrecep, Wvalue, out);
}

// round 3
// speedup vs baseline: 1.2139x; 1.2139x over previous
#include <cuda_runtime.h>

#define C    128
#define HID  512
#define TT   64      // tokens per CTA
#define NTH  256
#define OPT  4       // outputs per thread
#define HW   16384   // h*w per image

typedef unsigned long long u64;

struct Smem {
    float X[C][TT];      // residual t, feature-major
    float U[C][TT];      // scratch: u / y2 / k_chunk
    float Wht[C][TT];    // whitened activations
    float red1[16][TT];
    float red2[16][TT];
    float mu[TT];
    float rstd[TT];
};

// ---- f32x2 helpers (Blackwell packed fp32) ----
__device__ __forceinline__ u64 dup2(float w) {
    u64 r;
    asm("mov.b64 %0, {%1, %1};" : "=l"(r) : "f"(w));
    return r;
}
__device__ __forceinline__ void ffma2(u64& a, u64 x, u64 w) {
    asm("fma.rn.f32x2 %0, %1, %2, %0;" : "+l"(a) : "l"(x), "l"(w));
}
__device__ __forceinline__ float2 unpk(u64 v) {
    float lo, hi;
    asm("mov.b64 {%0, %1}, %2;" : "=f"(lo), "=f"(hi) : "l"(v));
    return make_float2(lo, hi);
}
__device__ __forceinline__ float sigm(float v) {
    return 1.0f / (1.0f + __expf(-v));
}

// LayerNorm over channel dim for all TT tokens; optional fused sigmoid(v)*v.
// Fully float4-vectorized over tokens.
__device__ __forceinline__ void layer_norm(Smem& sm, const float (*src)[TT],
                                           float (*dst)[TT],
                                           const float* __restrict__ g,
                                           const float* __restrict__ bta,
                                           bool sigmul)
{
    const int tid  = threadIdx.x;
    const int part = tid >> 4;          // 0..15, 8 channels each
    const int t4   = (tid & 15) * 4;    // 4 tokens
    float4 s1 = make_float4(0.f, 0.f, 0.f, 0.f);
    float4 s2 = make_float4(0.f, 0.f, 0.f, 0.f);
    #pragma unroll
    for (int k = 0; k < 8; k++) {
        float4 v = *reinterpret_cast<const float4*>(&src[part * 8 + k][t4]);
        s1.x += v.x; s1.y += v.y; s1.z += v.z; s1.w += v.w;
        s2.x += v.x * v.x; s2.y += v.y * v.y; s2.z += v.z * v.z; s2.w += v.w * v.w;
    }
    *reinterpret_cast<float4*>(&sm.red1[part][t4]) = s1;
    *reinterpret_cast<float4*>(&sm.red2[part][t4]) = s2;
    __syncthreads();
    if (tid < TT) {
        float a = 0.f, q = 0.f;
        #pragma unroll
        for (int p = 0; p < 16; p++) { a += sm.red1[p][tid]; q += sm.red2[p][tid]; }
        float mu  = a * (1.0f / C);
        float var = q * (1.0f / C) - mu * mu;
        sm.mu[tid]   = mu;
        sm.rstd[tid] = rsqrtf(var + 1e-5f);
    }
    __syncthreads();
    #pragma unroll
    for (int k = 0; k < (C * TT / 4) / NTH; k++) {   // 8 float4 per thread
        int idx = tid + k * NTH;
        int c = idx >> 4;
        int t = (idx & 15) * 4;
        float4 v  = *reinterpret_cast<const float4*>(&src[c][t]);
        float4 m  = *reinterpret_cast<const float4*>(&sm.mu[t]);
        float4 rs = *reinterpret_cast<const float4*>(&sm.rstd[t]);
        float gg = __ldg(g + c), bb = __ldg(bta + c);
        float4 o;
        o.x = (v.x - m.x) * rs.x * gg + bb;
        o.y = (v.y - m.y) * rs.y * gg + bb;
        o.z = (v.z - m.z) * rs.z * gg + bb;
        o.w = (v.w - m.w) * rs.w * gg + bb;
        if (sigmul) {
            o.x *= sigm(o.x); o.y *= sigm(o.y);
            o.z *= sigm(o.z); o.w *= sigm(o.w);
        }
        *reinterpret_cast<float4*>(&dst[c][t]) = o;
    }
}

// acc[4][OPT] (f32x2 pairs) += W[rowBase+o][colOff+c] * src[c][tok]
// thread: tg=tid&7 -> tokens {4tg..4tg+3, 32+4tg..32+4tg+3}; og=tid>>3 -> 4 outputs
template<int LD>
__device__ __forceinline__ void gemm2(u64 acc[4][OPT], const float (*src)[TT],
                                      const float* __restrict__ W,
                                      int rowBase, int colOff)
{
    const int tid = threadIdx.x;
    const int tg  = tid & 7;
    const int og  = tid >> 3;
    const int t0  = tg * 4;
    const float* w0 = W + (size_t)(rowBase + og * OPT) * LD + colOff;
    #pragma unroll 2
    for (int c = 0; c < C; c += 4) {
        float4 wq[OPT];
        #pragma unroll
        for (int j = 0; j < OPT; j++)
            wq[j] = __ldg(reinterpret_cast<const float4*>(w0 + j * LD + c));
        #pragma unroll
        for (int cc = 0; cc < 4; cc++) {
            ulonglong2 av = *reinterpret_cast<const ulonglong2*>(&src[c + cc][t0]);
            ulonglong2 bv = *reinterpret_cast<const ulonglong2*>(&src[c + cc][t0 + 32]);
            #pragma unroll
            for (int j = 0; j < OPT; j++) {
                float w = (&wq[j].x)[cc];
                u64 w2 = dup2(w);
                ffma2(acc[0][j], av.x, w2);
                ffma2(acc[1][j], av.y, w2);
                ffma2(acc[2][j], bv.x, w2);
                ffma2(acc[3][j], bv.y, w2);
            }
        }
    }
}

__device__ __forceinline__ void zero_acc(u64 acc[4][OPT]) {
    #pragma unroll
    for (int i = 0; i < 4; i++)
        #pragma unroll
        for (int j = 0; j < OPT; j++)
            acc[i][j] = 0ull;
}

// token base (first of the pair) for pair-index i
__device__ __forceinline__ int pair_tok(int t0, int i) {
    return t0 + (i >> 1) * 32 + (i & 1) * 2;
}

__global__ void __launch_bounds__(NTH, 2) rwkv_kernel(
    const float* __restrict__ x,
    const float* __restrict__ ln0_g, const float* __restrict__ ln0_b,
    const float* __restrict__ ln1_g, const float* __restrict__ ln1_b,
    const float* __restrict__ ln2_g, const float* __restrict__ ln2_b,
    const float* __restrict__ Wout,  const float* __restrict__ Wwhiten,
    const float* __restrict__ Wkey,  const float* __restrict__ Wrecep,
    const float* __restrict__ Wvalue,
    float* __restrict__ out)
{
    extern __shared__ char smraw[];
    Smem& sm = *reinterpret_cast<Smem*>(smraw);
    const int tid = threadIdx.x;
    const int tg  = tid & 7;
    const int og  = tid >> 3;
    const int t0  = tg * 4;
    const int tile = blockIdx.x;          // 0..1023
    const int b    = tile >> 8;
    const int hw0  = (tile & 255) * TT;
    const float* xb = x   + (size_t)b * C * HW + hw0;
    float*       ob = out + (size_t)b * C * HW + hw0;

    // Load tile (float4, coalesced over tokens)
    #pragma unroll
    for (int k = 0; k < (C * TT / 4) / NTH; k++) {
        int idx = tid + k * NTH;
        int c = idx >> 4, t = (idx & 15) * 4;
        *reinterpret_cast<float4*>(&sm.X[c][t]) =
            *reinterpret_cast<const float4*>(&xb[c * HW + t]);
    }
    __syncthreads();

    // t = ln0(x) (in place)
    layer_norm(sm, sm.X, sm.X, ln0_g, ln0_b, false);
    __syncthreads();

    // --- SpatialMix: att = W_out @ (sigmoid(y1)*y1), y1 = ln1(t); t += att
    layer_norm(sm, sm.X, sm.U, ln1_g, ln1_b, true);
    __syncthreads();
    {
        u64 acc[4][OPT];
        zero_acc(acc);
        gemm2<C>(acc, sm.U, Wout, 0, 0);
        #pragma unroll
        for (int j = 0; j < OPT; j++) {
            int ch = og * OPT + j;
            #pragma unroll
            for (int i = 0; i < 4; i++) {
                float2 v = unpk(acc[i][j]);
                float2* p = reinterpret_cast<float2*>(&sm.X[ch][pair_tok(t0, i)]);
                float2 o = *p;
                o.x += v.x; o.y += v.y;
                *p = o;
            }
        }
    }
    __syncthreads();

    // --- ChannelMix: y2 = ln2(t); wht = W_whiten @ y2
    layer_norm(sm, sm.X, sm.U, ln2_g, ln2_b, false);
    __syncthreads();
    {
        u64 acc[4][OPT];
        zero_acc(acc);
        gemm2<C>(acc, sm.U, Wwhiten, 0, 0);
        __syncthreads();   // all U reads done before U is reused below
        #pragma unroll
        for (int j = 0; j < OPT; j++) {
            int ch = og * OPT + j;
            #pragma unroll
            for (int i = 0; i < 4; i++)
                *reinterpret_cast<float2*>(&sm.Wht[ch][pair_tok(t0, i)]) =
                    unpk(acc[i][j]);
        }
    }
    __syncthreads();

    // k = relu(W_key @ wht)^2 in 4 chunks; kv += W_value[:,chunk] @ k_chunk
    u64 accKV[4][OPT];
    zero_acc(accKV);
    for (int ch4 = 0; ch4 < 4; ch4++) {
        u64 accK[4][OPT];
        zero_acc(accK);
        gemm2<C>(accK, sm.Wht, Wkey, ch4 * C, 0);
        __syncthreads();                 // previous chunk's U reads done
        #pragma unroll
        for (int j = 0; j < OPT; j++) {
            int ch = og * OPT + j;
            #pragma unroll
            for (int i = 0; i < 4; i++) {
                float2 v = unpk(accK[i][j]);
                v.x = (v.x > 0.f) ? v.x * v.x : 0.f;
                v.y = (v.y > 0.f) ? v.y * v.y : 0.f;
                *reinterpret_cast<float2*>(&sm.U[ch][pair_tok(t0, i)]) = v;
            }
        }
        __syncthreads();
        gemm2<HID>(accKV, sm.U, Wvalue, 0, ch4 * C);
    }

    // r = sigmoid(W_recep @ wht);  out = 2 * (t + r*kv)
    {
        u64 accR[4][OPT];
        zero_acc(accR);
        gemm2<C>(accR, sm.Wht, Wrecep, 0, 0);
        #pragma unroll
        for (int j = 0; j < OPT; j++) {
            int ch = og * OPT + j;
            #pragma unroll
            for (int i = 0; i < 4; i++) {
                int tk = pair_tok(t0, i);
                float2 rr = unpk(accR[i][j]);
                float2 kv = unpk(accKV[i][j]);
                float2 xv = *reinterpret_cast<const float2*>(&sm.X[ch][tk]);
                float2 o;
                o.x = 2.0f * (xv.x + sigm(rr.x) * kv.x);
                o.y = 2.0f * (xv.y + sigm(rr.y) * kv.y);
                *reinterpret_cast<float2*>(&ob[ch * HW + tk]) = o;
            }
        }
    }
}

extern "C" void kernel_launch(void* const* d_in, const int* in_sizes, int n_in,
                              void* d_out, int out_size)
{
    const float* x       = (const float*)d_in[0];
    const float* ln0_g   = (const float*)d_in[1];
    const float* ln0_b   = (const float*)d_in[2];
    const float* ln1_g   = (const float*)d_in[3];
    const float* ln1_b   = (const float*)d_in[4];
    const float* ln2_g   = (const float*)d_in[5];
    const float* ln2_b   = (const float*)d_in[6];
    const float* Wout    = (const float*)d_in[7];
    const float* Wwhiten = (const float*)d_in[8];
    const float* Wkey    = (const float*)d_in[9];
    const float* Wrecep  = (const float*)d_in[10];
    const float* Wvalue  = (const float*)d_in[11];
    float* out = (float*)d_out;

    cudaFuncSetAttribute(rwkv_kernel,
                         cudaFuncAttributeMaxDynamicSharedMemorySize,
                         (int)sizeof(Smem));
    rwkv_kernel<<<1024, NTH, sizeof(Smem)>>>(
        x, ln0_g, ln0_b, ln1_g, ln1_b, ln2_g, ln2_b,
        Wout, Wwhiten, Wkey, Wrecep, Wvalue, out);
}

// round 6
// speedup vs baseline: 4.0902x; 3.3696x over previous
#include <cuda_runtime.h>
#include <cuda_bf16.h>
#include <cstdint>

#define C    128
#define TT   64
#define NTH  256
#define HW   16384
#define ST   68          // X row stride in floats (272B, 16B-aligned)

#define WHALF 360448u    // 11 chunks * 32768B per hi (and per lo) image
__device__ __align__(16) unsigned char g_wfrag[2u * WHALF];

// ---- smem layout (bytes) ----
#define OFF_X    0                      // fp32 X[128][ST]          34816
#define OFF_BGH  34816                  // gen act tile hi (swz)    16384
#define OFF_BGL  (OFF_BGH + 16384)      // gen act tile lo          16384
#define OFF_BWH  (OFF_BGL + 16384)      // wht act tile hi          16384
#define OFF_RS   (OFF_BWH + 16384)      // sigmoid(r) bf16 [128][64]16384
#define OFF_RED1 (OFF_RS + 16384)
#define OFF_RED2 (OFF_RED1 + 4096)
#define OFF_MU   (OFF_RED2 + 4096)
#define OFF_RSTD (OFF_MU + 256)
#define SMEM_TOT (OFF_RSTD + 256)       // 109056

// ---- helpers ----
__device__ __forceinline__ uint32_t pack_bf(float lo, float hi) {
    uint32_t d;
    asm("cvt.rn.bf16x2.f32 %0, %1, %2;" : "=r"(d) : "f"(hi), "f"(lo));
    return d;
}
__device__ __forceinline__ float2 unpack_bf(uint32_t v) {
    __nv_bfloat162 h = *reinterpret_cast<__nv_bfloat162*>(&v);
    return make_float2(__bfloat162float(h.x), __bfloat162float(h.y));
}
__device__ __forceinline__ float sigm(float v) { return 1.0f / (1.0f + __expf(-v)); }

__device__ __forceinline__ void ldsm4t(uint32_t& r0, uint32_t& r1, uint32_t& r2,
                                       uint32_t& r3, uint32_t addr) {
    asm volatile("ldmatrix.sync.aligned.m8n8.x4.trans.shared.b16 {%0,%1,%2,%3}, [%4];"
                 : "=r"(r0), "=r"(r1), "=r"(r2), "=r"(r3) : "r"(addr));
}
__device__ __forceinline__ void mma16(float* d, const uint4& a, uint32_t b0, uint32_t b1) {
    asm volatile("mma.sync.aligned.m16n8k16.row.col.f32.bf16.bf16.f32 "
                 "{%0,%1,%2,%3}, {%4,%5,%6,%7}, {%8,%9}, {%0,%1,%2,%3};"
                 : "+f"(d[0]), "+f"(d[1]), "+f"(d[2]), "+f"(d[3])
                 : "r"(a.x), "r"(a.y), "r"(a.z), "r"(a.w), "r"(b0), "r"(b1));
}
__device__ __forceinline__ void zero8(float (*a)[4]) {
    #pragma unroll
    for (int i = 0; i < 8; i++)
        #pragma unroll
        for (int j = 0; j < 4; j++) a[i][j] = 0.f;
}

// D[16 out x 64 tok] for one chunk; A frags from frag-ordered global, B from swizzled smem.
// Terms: Ah*Bh + Al*Bh (+ Ah*Bl if USE_BL).
template<bool USE_BL>
__device__ __forceinline__ void gemm16(float (*acc)[4],
    const unsigned char* __restrict__ wfh, const unsigned char* __restrict__ wfl,
    uint32_t bh, uint32_t bl, int lane)
{
    const int grp  = lane >> 3, r8 = lane & 7;
    const int kadd = (grp & 1) * 8 + r8;
    const int cgrp = grp >> 1;
    uint32_t coff[4];
    #pragma unroll
    for (int ntp = 0; ntp < 4; ntp++)
        coff[ntp] = (uint32_t)(((ntp * 2 + cgrp) ^ r8) << 4);
    #pragma unroll 1
    for (int kt = 0; kt < 8; kt++) {
        uint4 Ah = *reinterpret_cast<const uint4*>(wfh + kt * 4096);
        uint4 Al = *reinterpret_cast<const uint4*>(wfl + kt * 4096);
        uint32_t rowb_h = bh + (uint32_t)((kt * 16 + kadd) * 128);
        uint32_t rowb_l = bl + (uint32_t)((kt * 16 + kadd) * 128);
        #pragma unroll
        for (int ntp = 0; ntp < 4; ntp++) {
            uint32_t b0, b1, b2, b3;
            ldsm4t(b0, b1, b2, b3, rowb_h + coff[ntp]);
            mma16(acc[2*ntp],   Ah, b0, b1);
            mma16(acc[2*ntp+1], Ah, b2, b3);
            mma16(acc[2*ntp],   Al, b0, b1);
            mma16(acc[2*ntp+1], Al, b2, b3);
            if (USE_BL) {
                uint32_t c0, c1, c2, c3;
                ldsm4t(c0, c1, c2, c3, rowb_l + coff[ntp]);
                mma16(acc[2*ntp],   Ah, c0, c1);
                mma16(acc[2*ntp+1], Ah, c2, c3);
            }
        }
    }
}

// ---- prep: fp32 weights -> fragment-ordered bf16 hi/lo images ----
// chunk q: 0=Wout 1=Wwhiten 2=Wrecep 3..6=Wkey rows ch*128.. 7..10=Wvalue cols ch*128..
// entry (q, kt, mt, lane): 16B = A-frag regs {a0,a1,a2,a3} for rows mt*16.., cols kt*16..
__global__ void __launch_bounds__(NTH) prep_kernel(
    const float* __restrict__ Wout, const float* __restrict__ Wwh,
    const float* __restrict__ Wkey, const float* __restrict__ Wrec,
    const float* __restrict__ Wval)
{
    int e = blockIdx.x * NTH + threadIdx.x;
    if (e >= 11 * 64 * 32) return;
    int lane = e & 31, mt = (e >> 5) & 7, kt = (e >> 8) & 7, q = e >> 11;
    int r  = lane >> 2;
    int cb = (lane & 3) * 2;
    float v[8];
    #pragma unroll
    for (int j = 0; j < 8; j++) {
        int row = mt * 16 + r + ((j >> 1) & 1) * 8;     // a1,a3 -> +8 rows
        int col = kt * 16 + cb + (j >> 2) * 8 + (j & 1);// a2,a3 -> +8 cols
        float w;
        if (q == 0)      w = Wout[row * 128 + col];
        else if (q == 1) w = Wwh[row * 128 + col];
        else if (q == 2) w = Wrec[row * 128 + col];
        else if (q <= 6) w = Wkey[((q - 3) * 128 + row) * 128 + col];
        else             w = Wval[row * 512 + (q - 7) * 128 + col];
        v[j] = w;
    }
    uint4 hi, lo;
    uint32_t* hp = &hi.x;
    uint32_t* lp = &lo.x;
    #pragma unroll
    for (int p = 0; p < 4; p++) {
        uint32_t h = pack_bf(v[2*p], v[2*p+1]);
        float2 hf = unpack_bf(h);
        hp[p] = h;
        lp[p] = pack_bf(v[2*p] - hf.x, v[2*p+1] - hf.y);
    }
    size_t off = (size_t)(((q * 8 + kt) * 8 + mt) * 32 + lane) * 16;
    *reinterpret_cast<uint4*>(g_wfrag + off)         = hi;
    *reinterpret_cast<uint4*>(g_wfrag + WHALF + off) = lo;
}

// ---- main ----
__global__ void __launch_bounds__(NTH, 2) rwkv_mma_kernel(
    const float* __restrict__ x,
    const float* __restrict__ ln0_g, const float* __restrict__ ln0_b,
    const float* __restrict__ ln1_g, const float* __restrict__ ln1_b,
    const float* __restrict__ ln2_g, const float* __restrict__ ln2_b,
    float* __restrict__ out)
{
    extern __shared__ char sm[];
    const int tid  = threadIdx.x;
    const int wid  = tid >> 5;
    const int lane = tid & 31;
    const uint32_t smb = (uint32_t)__cvta_generic_to_shared(sm);

    const int tile = blockIdx.x;
    const int b    = tile >> 8;
    const int hw0  = (tile & 255) * TT;
    const float* xb = x   + (size_t)b * C * HW + hw0;
    float*       ob = out + (size_t)b * C * HW + hw0;

    float* X    = (float*)(sm + OFF_X);
    float* red1 = (float*)(sm + OFF_RED1);
    float* red2 = (float*)(sm + OFF_RED2);
    float* muv  = (float*)(sm + OFF_MU);
    float* rsv  = (float*)(sm + OFF_RSTD);

    // load X tile (coalesced float4 over tokens)
    #pragma unroll
    for (int k = 0; k < 8; k++) {
        int idx = tid + k * NTH;
        int c = idx >> 4, t = (idx & 15) * 4;
        *reinterpret_cast<float4*>(&X[c * ST + t]) =
            *reinterpret_cast<const float4*>(&xb[c * HW + t]);
    }
    __syncthreads();

    // LN over channels. mode 0: fp32 in-place; mode 1: sig(v)*v -> BGH/BGL; mode 2: v -> BGH/BGL
    auto layer_norm = [&](const float* g, const float* bb_, int mode) {
        const int part = tid >> 4;
        const int t4   = (tid & 15) * 4;
        float4 s1 = make_float4(0,0,0,0), s2 = make_float4(0,0,0,0);
        #pragma unroll
        for (int k = 0; k < 8; k++) {
            float4 v = *reinterpret_cast<const float4*>(&X[(part * 8 + k) * ST + t4]);
            s1.x += v.x; s1.y += v.y; s1.z += v.z; s1.w += v.w;
            s2.x += v.x*v.x; s2.y += v.y*v.y; s2.z += v.z*v.z; s2.w += v.w*v.w;
        }
        *reinterpret_cast<float4*>(&red1[part * 64 + t4]) = s1;
        *reinterpret_cast<float4*>(&red2[part * 64 + t4]) = s2;
        __syncthreads();
        if (tid < TT) {
            float a = 0.f, qq = 0.f;
            #pragma unroll
            for (int p = 0; p < 16; p++) { a += red1[p * 64 + tid]; qq += red2[p * 64 + tid]; }
            float mu = a * (1.0f / C);
            float var = qq * (1.0f / C) - mu * mu;
            muv[tid] = mu; rsv[tid] = rsqrtf(var + 1e-5f);
        }
        __syncthreads();
        #pragma unroll
        for (int k = 0; k < 8; k++) {
            int idx = tid + k * NTH;
            int c = idx >> 4, t0 = (idx & 15) * 4;
            float4 v  = *reinterpret_cast<const float4*>(&X[c * ST + t0]);
            float4 m  = *reinterpret_cast<const float4*>(&muv[t0]);
            float4 rs = *reinterpret_cast<const float4*>(&rsv[t0]);
            float gg = __ldg(g + c), bbv = __ldg(bb_ + c);
            float o0 = (v.x - m.x) * rs.x * gg + bbv;
            float o1 = (v.y - m.y) * rs.y * gg + bbv;
            float o2 = (v.z - m.z) * rs.z * gg + bbv;
            float o3 = (v.w - m.w) * rs.w * gg + bbv;
            if (mode == 0) {
                *reinterpret_cast<float4*>(&X[c * ST + t0]) = make_float4(o0,o1,o2,o3);
            } else {
                if (mode == 1) { o0 *= sigm(o0); o1 *= sigm(o1); o2 *= sigm(o2); o3 *= sigm(o3); }
                // swizzled channel-major store: row c (128B), tokens t0..t0+3
                uint32_t a_off = (uint32_t)(c * 128 + (((t0 >> 3) ^ (c & 7)) << 4) + ((t0 & 4) << 1));
                uint32_t h0 = pack_bf(o0, o1), h1 = pack_bf(o2, o3);
                *reinterpret_cast<uint2*>(sm + OFF_BGH + a_off) = make_uint2(h0, h1);
                float2 f0 = unpack_bf(h0), f1 = unpack_bf(h1);
                uint32_t l0 = pack_bf(o0 - f0.x, o1 - f0.y);
                uint32_t l1 = pack_bf(o2 - f1.x, o3 - f1.y);
                *reinterpret_cast<uint2*>(sm + OFF_BGL + a_off) = make_uint2(l0, l1);
            }
        }
    };

    const unsigned char* wf = g_wfrag;
    const int c0 = wid * 16 + (lane >> 2);     // this lane's first out-row
    const int nb = (lane & 3) * 2;             // this lane's token offset within an n-tile
    // entry stride: mt (=wid) 512B, kt 4096B, q 32768B; lane*16 within entry
    auto wptr = [&](int q) { return wf + (size_t)(q * 64 + wid) * 512 + (size_t)lane * 16; };

    float acc[8][4];

    layer_norm(ln0_g, ln0_b, 0);
    __syncthreads();
    layer_norm(ln1_g, ln1_b, 1);
    __syncthreads();

    // att = Wout @ y1s ; X += att
    zero8(acc);
    gemm16<true>(acc, wptr(0), wptr(0) + WHALF, smb + OFF_BGH, smb + OFF_BGL, lane);
    #pragma unroll
    for (int nt = 0; nt < 8; nt++) {
        int n = nt * 8 + nb;
        float2* p0 = reinterpret_cast<float2*>(&X[c0 * ST + n]);
        float2* p1 = reinterpret_cast<float2*>(&X[(c0 + 8) * ST + n]);
        float2 a0 = *p0, a1 = *p1;
        a0.x += acc[nt][0]; a0.y += acc[nt][1];
        a1.x += acc[nt][2]; a1.y += acc[nt][3];
        *p0 = a0; *p1 = a1;
    }
    __syncthreads();

    layer_norm(ln2_g, ln2_b, 2);
    __syncthreads();

    // wht = Wwhiten @ y2 -> BWH (hi only)
    zero8(acc);
    gemm16<true>(acc, wptr(1), wptr(1) + WHALF, smb + OFF_BGH, smb + OFF_BGL, lane);
    __syncthreads();            // all BGH/BGL reads done before reuse below; BWH writes next
    #pragma unroll
    for (int nt = 0; nt < 8; nt++) {
        uint32_t a_off = (uint32_t)((nt ^ (c0 & 7)) << 4) + (uint32_t)((lane & 3) * 4);
        uint32_t a_off8 = (uint32_t)((nt ^ ((c0 + 8) & 7)) << 4) + (uint32_t)((lane & 3) * 4);
        *reinterpret_cast<uint32_t*>(sm + OFF_BWH + c0 * 128 + a_off) =
            pack_bf(acc[nt][0], acc[nt][1]);
        *reinterpret_cast<uint32_t*>(sm + OFF_BWH + (c0 + 8) * 128 + a_off8) =
            pack_bf(acc[nt][2], acc[nt][3]);
    }
    __syncthreads();

    // r = sigmoid(Wrecep @ wht) -> RS (bf16)
    zero8(acc);
    gemm16<false>(acc, wptr(2), wptr(2) + WHALF, smb + OFF_BWH, 0u, lane);
    #pragma unroll
    for (int nt = 0; nt < 8; nt++) {
        int n = nt * 8 + nb;
        *reinterpret_cast<uint32_t*>(sm + OFF_RS + c0 * 128 + n * 2) =
            pack_bf(sigm(acc[nt][0]), sigm(acc[nt][1]));
        *reinterpret_cast<uint32_t*>(sm + OFF_RS + (c0 + 8) * 128 + n * 2) =
            pack_bf(sigm(acc[nt][2]), sigm(acc[nt][3]));
    }

    // kv accumulation over 4 hidden chunks
    float accKV[8][4];
    zero8(accKV);
    #pragma unroll 1
    for (int ch = 0; ch < 4; ch++) {
        zero8(acc);
        gemm16<false>(acc, wptr(3 + ch), wptr(3 + ch) + WHALF, smb + OFF_BWH, 0u, lane);
        __syncthreads();        // prior value-gemm reads of BGH done (all warps)
        #pragma unroll
        for (int nt = 0; nt < 8; nt++) {
            float k0 = acc[nt][0] > 0.f ? acc[nt][0] * acc[nt][0] : 0.f;
            float k1 = acc[nt][1] > 0.f ? acc[nt][1] * acc[nt][1] : 0.f;
            float k2 = acc[nt][2] > 0.f ? acc[nt][2] * acc[nt][2] : 0.f;
            float k3 = acc[nt][3] > 0.f ? acc[nt][3] * acc[nt][3] : 0.f;
            uint32_t a_off = (uint32_t)((nt ^ (c0 & 7)) << 4) + (uint32_t)((lane & 3) * 4);
            uint32_t a_off8 = (uint32_t)((nt ^ ((c0 + 8) & 7)) << 4) + (uint32_t)((lane & 3) * 4);
            *reinterpret_cast<uint32_t*>(sm + OFF_BGH + c0 * 128 + a_off) = pack_bf(k0, k1);
            *reinterpret_cast<uint32_t*>(sm + OFF_BGH + (c0 + 8) * 128 + a_off8) = pack_bf(k2, k3);
        }
        __syncthreads();
        gemm16<false>(accKV, wptr(7 + ch), wptr(7 + ch) + WHALF, smb + OFF_BGH, 0u, lane);
    }

    // out = 2 * (X + r * kv)
    #pragma unroll
    for (int nt = 0; nt < 8; nt++) {
        int n = nt * 8 + nb;
        float2 r0 = unpack_bf(*reinterpret_cast<uint32_t*>(sm + OFF_RS + c0 * 128 + n * 2));
        float2 r1 = unpack_bf(*reinterpret_cast<uint32_t*>(sm + OFF_RS + (c0 + 8) * 128 + n * 2));
        float2 x0 = *reinterpret_cast<float2*>(&X[c0 * ST + n]);
        float2 x1 = *reinterpret_cast<float2*>(&X[(c0 + 8) * ST + n]);
        float2 o0, o1;
        o0.x = 2.0f * (x0.x + r0.x * accKV[nt][0]);
        o0.y = 2.0f * (x0.y + r0.y * accKV[nt][1]);
        o1.x = 2.0f * (x1.x + r1.x * accKV[nt][2]);
        o1.y = 2.0f * (x1.y + r1.y * accKV[nt][3]);
        *reinterpret_cast<float2*>(&ob[c0 * HW + n]) = o0;
        *reinterpret_cast<float2*>(&ob[(c0 + 8) * HW + n]) = o1;
    }
}

extern "C" void kernel_launch(void* const* d_in, const int* in_sizes, int n_in,
                              void* d_out, int out_size)
{
    const float* x       = (const float*)d_in[0];
    const float* ln0_g   = (const float*)d_in[1];
    const float* ln0_b   = (const float*)d_in[2];
    const float* ln1_g   = (const float*)d_in[3];
    const float* ln1_b   = (const float*)d_in[4];
    const float* ln2_g   = (const float*)d_in[5];
    const float* ln2_b   = (const float*)d_in[6];
    const float* Wout    = (const float*)d_in[7];
    const float* Wwhiten = (const float*)d_in[8];
    const float* Wkey    = (const float*)d_in[9];
    const float* Wrecep  = (const float*)d_in[10];
    const float* Wvalue  = (const float*)d_in[11];
    float* out = (float*)d_out;

    prep_kernel<<<88, NTH>>>(Wout, Wwhiten, Wkey, Wrecep, Wvalue);

    cudaFuncSetAttribute(rwkv_mma_kernel,
                         cudaFuncAttributeMaxDynamicSharedMemorySize, SMEM_TOT);
    rwkv_mma_kernel<<<1024, NTH, SMEM_TOT>>>(
        x, ln0_g, ln0_b, ln1_g, ln1_b, ln2_g, ln2_b, out);
}

// round 7
// speedup vs baseline: 4.6625x; 1.1399x over previous
#include <cuda_runtime.h>
#include <cuda_fp16.h>
#include <cstdint>

#define C    128
#define TT   64
#define NTH  256
#define HW   16384
#define ST   68          // X row stride in floats (272B, 16B-aligned)

#define WHALF 360448u    // 11 chunks * 32768B per hi (and per lo) image
__device__ __align__(16) unsigned char g_wfrag[2u * WHALF];

// ---- smem layout (bytes) ----
#define OFF_X    0                      // fp32 X[128][ST]      34816
#define OFF_BA   34816                  // act tile (y1/y2) + k-chunk buf A
#define OFF_BW   (OFF_BA + 16384)       // wht tile
#define OFF_BK   (OFF_BW + 16384)       // k-chunk buf B
#define OFF_RS   (OFF_BK + 16384)       // sigmoid(r) fp16 [128][64]
#define OFF_RED1 (OFF_RS + 16384)
#define OFF_RED2 (OFF_RED1 + 4096)
#define OFF_MU   (OFF_RED2 + 4096)
#define OFF_RSTD (OFF_MU + 256)
#define SMEM_TOT (OFF_RSTD + 256)       // 109056

// ---- helpers ----
__device__ __forceinline__ uint32_t pack_h(float lo, float hi) {
    uint32_t d;
    asm("cvt.rn.f16x2.f32 %0, %1, %2;" : "=r"(d) : "f"(hi), "f"(lo));
    return d;
}
__device__ __forceinline__ float2 unpack_h(uint32_t v) {
    __half2 h = *reinterpret_cast<__half2*>(&v);
    return __half22float2(h);
}
__device__ __forceinline__ float sigm(float v) { return 1.0f / (1.0f + __expf(-v)); }

__device__ __forceinline__ void ldsm4t(uint32_t& r0, uint32_t& r1, uint32_t& r2,
                                       uint32_t& r3, uint32_t addr) {
    asm volatile("ldmatrix.sync.aligned.m8n8.x4.trans.shared.b16 {%0,%1,%2,%3}, [%4];"
                 : "=r"(r0), "=r"(r1), "=r"(r2), "=r"(r3) : "r"(addr));
}
__device__ __forceinline__ void mma16(float* d, const uint4& a, uint32_t b0, uint32_t b1) {
    asm volatile("mma.sync.aligned.m16n8k16.row.col.f32.f16.f16.f32 "
                 "{%0,%1,%2,%3}, {%4,%5,%6,%7}, {%8,%9}, {%0,%1,%2,%3};"
                 : "+f"(d[0]), "+f"(d[1]), "+f"(d[2]), "+f"(d[3])
                 : "r"(a.x), "r"(a.y), "r"(a.z), "r"(a.w), "r"(b0), "r"(b1));
}
__device__ __forceinline__ void zero8(float (*a)[4]) {
    #pragma unroll
    for (int i = 0; i < 8; i++)
        #pragma unroll
        for (int j = 0; j < 4; j++) a[i][j] = 0.f;
}

// D[16 out x 64 tok]; 2 terms: Ah*Bh + Al*Bh. ILP: 4 ldsm batched, then 8+8
// independent mma (same-acc reuse distance = 8).
__device__ __forceinline__ void gemm16(float (*acc)[4],
    const unsigned char* __restrict__ wfh, const unsigned char* __restrict__ wfl,
    uint32_t bh, int lane)
{
    const int grp  = lane >> 3, r8 = lane & 7;
    const int kadd = (grp & 1) * 8 + r8;
    const int cgrp = grp >> 1;
    uint32_t coff[4];
    #pragma unroll
    for (int ntp = 0; ntp < 4; ntp++)
        coff[ntp] = (uint32_t)(((ntp * 2 + cgrp) ^ r8) << 4);
    #pragma unroll 2
    for (int kt = 0; kt < 8; kt++) {
        uint4 Ah = *reinterpret_cast<const uint4*>(wfh + kt * 4096);
        uint4 Al = *reinterpret_cast<const uint4*>(wfl + kt * 4096);
        uint32_t rowb = bh + (uint32_t)((kt * 16 + kadd) * 128);
        uint32_t b[16];
        #pragma unroll
        for (int ntp = 0; ntp < 4; ntp++)
            ldsm4t(b[4*ntp], b[4*ntp+1], b[4*ntp+2], b[4*ntp+3], rowb + coff[ntp]);
        #pragma unroll
        for (int ntp = 0; ntp < 4; ntp++) {
            mma16(acc[2*ntp],   Ah, b[4*ntp],   b[4*ntp+1]);
            mma16(acc[2*ntp+1], Ah, b[4*ntp+2], b[4*ntp+3]);
        }
        #pragma unroll
        for (int ntp = 0; ntp < 4; ntp++) {
            mma16(acc[2*ntp],   Al, b[4*ntp],   b[4*ntp+1]);
            mma16(acc[2*ntp+1], Al, b[4*ntp+2], b[4*ntp+3]);
        }
    }
}

// ---- prep: fp32 weights -> fragment-ordered fp16 hi/lo images ----
// chunk q: 0=Wout 1=Wwhiten 2=Wrecep 3..6=Wkey rows ch*128.. 7..10=Wvalue cols ch*128..
__global__ void __launch_bounds__(NTH) prep_kernel(
    const float* __restrict__ Wout, const float* __restrict__ Wwh,
    const float* __restrict__ Wkey, const float* __restrict__ Wrec,
    const float* __restrict__ Wval)
{
    int e = blockIdx.x * NTH + threadIdx.x;
    if (e >= 11 * 64 * 32) return;
    int lane = e & 31, mt = (e >> 5) & 7, kt = (e >> 8) & 7, q = e >> 11;
    int r  = lane >> 2;
    int cb = (lane & 3) * 2;
    float v[8];
    #pragma unroll
    for (int j = 0; j < 8; j++) {
        int row = mt * 16 + r + ((j >> 1) & 1) * 8;
        int col = kt * 16 + cb + (j >> 2) * 8 + (j & 1);
        float w;
        if (q == 0)      w = Wout[row * 128 + col];
        else if (q == 1) w = Wwh[row * 128 + col];
        else if (q == 2) w = Wrec[row * 128 + col];
        else if (q <= 6) w = Wkey[((q - 3) * 128 + row) * 128 + col];
        else             w = Wval[row * 512 + (q - 7) * 128 + col];
        v[j] = w;
    }
    uint4 hi, lo;
    uint32_t* hp = &hi.x;
    uint32_t* lp = &lo.x;
    #pragma unroll
    for (int p = 0; p < 4; p++) {
        uint32_t h = pack_h(v[2*p], v[2*p+1]);
        float2 hf = unpack_h(h);
        hp[p] = h;
        lp[p] = pack_h(v[2*p] - hf.x, v[2*p+1] - hf.y);
    }
    size_t off = (size_t)(((q * 8 + kt) * 8 + mt) * 32 + lane) * 16;
    *reinterpret_cast<uint4*>(g_wfrag + off)         = hi;
    *reinterpret_cast<uint4*>(g_wfrag + WHALF + off) = lo;
}

// ---- main ----
__global__ void __launch_bounds__(NTH, 2) rwkv_mma_kernel(
    const float* __restrict__ x,
    const float* __restrict__ ln0_g, const float* __restrict__ ln0_b,
    const float* __restrict__ ln1_g, const float* __restrict__ ln1_b,
    const float* __restrict__ ln2_g, const float* __restrict__ ln2_b,
    float* __restrict__ out)
{
    extern __shared__ char sm[];
    const int tid  = threadIdx.x;
    const int wid  = tid >> 5;
    const int lane = tid & 31;
    const uint32_t smb = (uint32_t)__cvta_generic_to_shared(sm);

    const int tile = blockIdx.x;
    const int b    = tile >> 8;
    const int hw0  = (tile & 255) * TT;
    const float* xb = x   + (size_t)b * C * HW + hw0;
    float*       ob = out + (size_t)b * C * HW + hw0;

    float* X    = (float*)(sm + OFF_X);
    float* red1 = (float*)(sm + OFF_RED1);
    float* red2 = (float*)(sm + OFF_RED2);
    float* muv  = (float*)(sm + OFF_MU);
    float* rsv  = (float*)(sm + OFF_RSTD);

    // load X tile (coalesced float4 over tokens)
    #pragma unroll
    for (int k = 0; k < 8; k++) {
        int idx = tid + k * NTH;
        int c = idx >> 4, t = (idx & 15) * 4;
        *reinterpret_cast<float4*>(&X[c * ST + t]) =
            *reinterpret_cast<const float4*>(&xb[c * HW + t]);
    }
    __syncthreads();

    // LN over channels. mode 0: fp32 in-place; mode 1: sig(v)*v -> BA; mode 2: v -> BA
    auto layer_norm = [&](const float* g, const float* bb_, int mode) {
        const int part = tid >> 4;
        const int t4   = (tid & 15) * 4;
        float4 s1 = make_float4(0,0,0,0), s2 = make_float4(0,0,0,0);
        #pragma unroll
        for (int k = 0; k < 8; k++) {
            float4 v = *reinterpret_cast<const float4*>(&X[(part * 8 + k) * ST + t4]);
            s1.x += v.x; s1.y += v.y; s1.z += v.z; s1.w += v.w;
            s2.x += v.x*v.x; s2.y += v.y*v.y; s2.z += v.z*v.z; s2.w += v.w*v.w;
        }
        *reinterpret_cast<float4*>(&red1[part * 64 + t4]) = s1;
        *reinterpret_cast<float4*>(&red2[part * 64 + t4]) = s2;
        __syncthreads();
        if (tid < TT) {
            float a = 0.f, qq = 0.f;
            #pragma unroll
            for (int p = 0; p < 16; p++) { a += red1[p * 64 + tid]; qq += red2[p * 64 + tid]; }
            float mu = a * (1.0f / C);
            float var = qq * (1.0f / C) - mu * mu;
            muv[tid] = mu; rsv[tid] = rsqrtf(var + 1e-5f);
        }
        __syncthreads();
        #pragma unroll
        for (int k = 0; k < 8; k++) {
            int idx = tid + k * NTH;
            int c = idx >> 4, t0 = (idx & 15) * 4;
            float4 v  = *reinterpret_cast<const float4*>(&X[c * ST + t0]);
            float4 m  = *reinterpret_cast<const float4*>(&muv[t0]);
            float4 rs = *reinterpret_cast<const float4*>(&rsv[t0]);
            float gg = __ldg(g + c), bbv = __ldg(bb_ + c);
            float o0 = (v.x - m.x) * rs.x * gg + bbv;
            float o1 = (v.y - m.y) * rs.y * gg + bbv;
            float o2 = (v.z - m.z) * rs.z * gg + bbv;
            float o3 = (v.w - m.w) * rs.w * gg + bbv;
            if (mode == 0) {
                *reinterpret_cast<float4*>(&X[c * ST + t0]) = make_float4(o0,o1,o2,o3);
            } else {
                if (mode == 1) { o0 *= sigm(o0); o1 *= sigm(o1); o2 *= sigm(o2); o3 *= sigm(o3); }
                uint32_t a_off = (uint32_t)(c * 128 + (((t0 >> 3) ^ (c & 7)) << 4) + ((t0 & 4) << 1));
                *reinterpret_cast<uint2*>(sm + OFF_BA + a_off) =
                    make_uint2(pack_h(o0, o1), pack_h(o2, o3));
            }
        }
    };

    const unsigned char* wf = g_wfrag;
    const int c0 = wid * 16 + (lane >> 2);
    const int nb = (lane & 3) * 2;
    auto wptr = [&](int q) { return wf + (size_t)(q * 64 + wid) * 512 + (size_t)lane * 16; };

    float acc[8][4];

    layer_norm(ln0_g, ln0_b, 0);
    __syncthreads();
    layer_norm(ln1_g, ln1_b, 1);
    __syncthreads();

    // att = Wout @ y1s ; X += att
    zero8(acc);
    gemm16(acc, wptr(0), wptr(0) + WHALF, smb + OFF_BA, lane);
    #pragma unroll
    for (int nt = 0; nt < 8; nt++) {
        int n = nt * 8 + nb;
        float2* p0 = reinterpret_cast<float2*>(&X[c0 * ST + n]);
        float2* p1 = reinterpret_cast<float2*>(&X[(c0 + 8) * ST + n]);
        float2 a0 = *p0, a1 = *p1;
        a0.x += acc[nt][0]; a0.y += acc[nt][1];
        a1.x += acc[nt][2]; a1.y += acc[nt][3];
        *p0 = a0; *p1 = a1;
    }
    __syncthreads();

    layer_norm(ln2_g, ln2_b, 2);
    __syncthreads();

    // wht = Wwhiten @ y2 -> BW (fp16)
    zero8(acc);
    gemm16(acc, wptr(1), wptr(1) + WHALF, smb + OFF_BA, lane);
    #pragma unroll
    for (int nt = 0; nt < 8; nt++) {
        uint32_t a_off  = (uint32_t)((nt ^ (c0 & 7)) << 4) + (uint32_t)((lane & 3) * 4);
        uint32_t a_off8 = (uint32_t)((nt ^ ((c0 + 8) & 7)) << 4) + (uint32_t)((lane & 3) * 4);
        *reinterpret_cast<uint32_t*>(sm + OFF_BW + c0 * 128 + a_off) =
            pack_h(acc[nt][0], acc[nt][1]);
        *reinterpret_cast<uint32_t*>(sm + OFF_BW + (c0 + 8) * 128 + a_off8) =
            pack_h(acc[nt][2], acc[nt][3]);
    }
    __syncthreads();   // BW visible to all; all BA reads (whiten) complete

    // r = sigmoid(Wrecep @ wht) -> RS (fp16, same-thread readback)
    zero8(acc);
    gemm16(acc, wptr(2), wptr(2) + WHALF, smb + OFF_BW, lane);
    #pragma unroll
    for (int nt = 0; nt < 8; nt++) {
        int n = nt * 8 + nb;
        *reinterpret_cast<uint32_t*>(sm + OFF_RS + c0 * 128 + n * 2) =
            pack_h(sigm(acc[nt][0]), sigm(acc[nt][1]));
        *reinterpret_cast<uint32_t*>(sm + OFF_RS + (c0 + 8) * 128 + n * 2) =
            pack_h(sigm(acc[nt][2]), sigm(acc[nt][3]));
    }

    // kv over 4 hidden chunks; k tiles double-buffered BA/BK (1 sync per chunk)
    float accKV[8][4];
    zero8(accKV);
    const uint32_t kbuf[2] = { smb + OFF_BA, smb + OFF_BK };
    const int      kbo[2]  = { OFF_BA, OFF_BK };
    #pragma unroll 1
    for (int ch = 0; ch < 4; ch++) {
        zero8(acc);
        gemm16(acc, wptr(3 + ch), wptr(3 + ch) + WHALF, smb + OFF_BW, lane);
        char* bk = sm + kbo[ch & 1];
        #pragma unroll
        for (int nt = 0; nt < 8; nt++) {
            float k0 = acc[nt][0] > 0.f ? acc[nt][0] * acc[nt][0] : 0.f;
            float k1 = acc[nt][1] > 0.f ? acc[nt][1] * acc[nt][1] : 0.f;
            float k2 = acc[nt][2] > 0.f ? acc[nt][2] * acc[nt][2] : 0.f;
            float k3 = acc[nt][3] > 0.f ? acc[nt][3] * acc[nt][3] : 0.f;
            uint32_t a_off  = (uint32_t)((nt ^ (c0 & 7)) << 4) + (uint32_t)((lane & 3) * 4);
            uint32_t a_off8 = (uint32_t)((nt ^ ((c0 + 8) & 7)) << 4) + (uint32_t)((lane & 3) * 4);
            *reinterpret_cast<uint32_t*>(bk + c0 * 128 + a_off)        = pack_h(k0, k1);
            *reinterpret_cast<uint32_t*>(bk + (c0 + 8) * 128 + a_off8) = pack_h(k2, k3);
        }
        __syncthreads();
        gemm16(accKV, wptr(7 + ch), wptr(7 + ch) + WHALF, kbuf[ch & 1], lane);
    }

    // out = 2 * (X + r * kv)
    #pragma unroll
    for (int nt = 0; nt < 8; nt++) {
        int n = nt * 8 + nb;
        float2 r0 = unpack_h(*reinterpret_cast<uint32_t*>(sm + OFF_RS + c0 * 128 + n * 2));
        float2 r1 = unpack_h(*reinterpret_cast<uint32_t*>(sm + OFF_RS + (c0 + 8) * 128 + n * 2));
        float2 x0 = *reinterpret_cast<float2*>(&X[c0 * ST + n]);
        float2 x1 = *reinterpret_cast<float2*>(&X[(c0 + 8) * ST + n]);
        float2 o0, o1;
        o0.x = 2.0f * (x0.x + r0.x * accKV[nt][0]);
        o0.y = 2.0f * (x0.y + r0.y * accKV[nt][1]);
        o1.x = 2.0f * (x1.x + r1.x * accKV[nt][2]);
        o1.y = 2.0f * (x1.y + r1.y * accKV[nt][3]);
        *reinterpret_cast<float2*>(&ob[c0 * HW + n]) = o0;
        *reinterpret_cast<float2*>(&ob[(c0 + 8) * HW + n]) = o1;
    }
}

extern "C" void kernel_launch(void* const* d_in, const int* in_sizes, int n_in,
                              void* d_out, int out_size)
{
    const float* x       = (const float*)d_in[0];
    const float* ln0_g   = (const float*)d_in[1];
    const float* ln0_b   = (const float*)d_in[2];
    const float* ln1_g   = (const float*)d_in[3];
    const float* ln1_b   = (const float*)d_in[4];
    const float* ln2_g   = (const float*)d_in[5];
    const float* ln2_b   = (const float*)d_in[6];
    const float* Wout    = (const float*)d_in[7];
    const float* Wwhiten = (const float*)d_in[8];
    const float* Wkey    = (const float*)d_in[9];
    const float* Wrecep  = (const float*)d_in[10];
    const float* Wvalue  = (const float*)d_in[11];
    float* out = (float*)d_out;

    prep_kernel<<<88, NTH>>>(Wout, Wwhiten, Wkey, Wrecep, Wvalue);

    cudaFuncSetAttribute(rwkv_mma_kernel,
                         cudaFuncAttributeMaxDynamicSharedMemorySize, SMEM_TOT);
    rwkv_mma_kernel<<<1024, NTH, SMEM_TOT>>>(
        x, ln0_g, ln0_b, ln1_g, ln1_b, ln2_g, ln2_b, out);
}